// round 15
// baseline (speedup 1.0000x reference)
#include <cuda_runtime.h>
#include <cstdint>

#define N_NODES   1000000
#define DIM       128
#define B_GRAPHS  2048
#define TAIL      224     // per-graph rows pinned L2-sticky for pass-2 reuse

// Scratch (no cudaMalloc allowed): transposed W for coalesced GEMM reads
__device__ float g_Wt[DIM * DIM];

__global__ void transpose_W_kernel(const float* __restrict__ W) {
    int i = blockIdx.x * blockDim.x + threadIdx.x;
    if (i < DIM * DIM) {
        int j = i >> 7;
        int k = i & (DIM - 1);
        g_Wt[k * DIM + j] = W[i];
    }
}

// ---- 32-byte loads with L2 eviction-priority (sm_103a: needs .v4.b64) ------
__device__ __forceinline__ void ld32_evict_first_acc(const void* p, float* f) {
    unsigned long long a, b, c, d;
    asm("ld.global.nc.L2::evict_first.v4.b64 {%0,%1,%2,%3}, [%4];"
        : "=l"(a), "=l"(b), "=l"(c), "=l"(d) : "l"(p));
    f[0] += __uint_as_float((unsigned)a); f[1] += __uint_as_float((unsigned)(a >> 32));
    f[2] += __uint_as_float((unsigned)b); f[3] += __uint_as_float((unsigned)(b >> 32));
    f[4] += __uint_as_float((unsigned)c); f[5] += __uint_as_float((unsigned)(c >> 32));
    f[6] += __uint_as_float((unsigned)d); f[7] += __uint_as_float((unsigned)(d >> 32));
}
__device__ __forceinline__ void ld32_evict_last_acc(const void* p, float* f) {
    unsigned long long a, b, c, d;
    asm("ld.global.nc.L2::evict_last.v4.b64 {%0,%1,%2,%3}, [%4];"
        : "=l"(a), "=l"(b), "=l"(c), "=l"(d) : "l"(p));
    f[0] += __uint_as_float((unsigned)a); f[1] += __uint_as_float((unsigned)(a >> 32));
    f[2] += __uint_as_float((unsigned)b); f[3] += __uint_as_float((unsigned)(b >> 32));
    f[4] += __uint_as_float((unsigned)c); f[5] += __uint_as_float((unsigned)(c >> 32));
    f[6] += __uint_as_float((unsigned)d); f[7] += __uint_as_float((unsigned)(d >> 32));
}

// ---------------------------------------------------------------------------
// Fused kernel (R8 direct-LDG engine + L2 residency steering):
//   pass 1: segment sum with 32B loads. 16 lanes x 32B = one 512B row;
//           thread t owns row-slot t>>4 (8 rows/iter) and dim-columns
//           8*(t&15)..+7. Head rows: evict_first (no L2 pollution).
//           Last TAIL rows: evict_last (pinned for pass 2).
//   GEMM:   vn = vn_h + relu((vn_h + pool) @ W^T + b)
//   pass 2: REVERSE float4 stream with .cs (tail rows hit the sticky lines).
// ---------------------------------------------------------------------------
__global__ void __launch_bounds__(128)
fused_vn_kernel(const float* __restrict__ h,
                const float* __restrict__ vn_h,
                const float* __restrict__ b,
                const int*   __restrict__ seg,
                float*       __restrict__ vn_out,
                float*       __restrict__ h_out) {
    __shared__ float spool[8][DIM];   // 8 row-slot partials
    __shared__ float sx[DIM];         // GEMM input row
    __shared__ float svn[DIM];        // final vn row
    __shared__ int   sbounds[2];

    int g  = blockIdx.x;
    int t  = threadIdx.x;
    int rw = t >> 4;                  // row slot 0..7 (pass 1)
    int ck = t & 15;                  // 32B chunk within row (pass 1)
    int sg = t >> 5;                  // warp 0..3 (pass 2)
    int ln = t & 31;                  // float4 lane (pass 2)

    // --- bounds via binary search (sorted seg -> contiguous range)
    if (t < 2) {
        int target = g + t;
        int lo = 0, hi = N_NODES;
        while (lo < hi) {
            int mid = (lo + hi) >> 1;
            if (__ldg(&seg[mid]) < target) lo = mid + 1;
            else                           hi = mid;
        }
        sbounds[t] = lo;
    }
    __syncthreads();
    int start = sbounds[0];
    int end   = sbounds[1];
    int tst   = end - TAIL; if (tst < start) tst = start;   // sticky-tail start

    // --- pass 1: segment sum. evict_first head, evict_last tail.
    float acc[8];
    #pragma unroll
    for (int j = 0; j < 8; ++j) acc[j] = 0.f;

    const char* hrow = (const char*)h + (size_t)ck * 32;
    int r = start + rw;
    #pragma unroll 4
    for (; r < tst; r += 8)
        ld32_evict_first_acc(hrow + (size_t)r * 512, acc);
    #pragma unroll 4
    for (; r < end; r += 8)
        ld32_evict_last_acc(hrow + (size_t)r * 512, acc);

    // --- reduce 8 row-slot partials -> pool[t]
    #pragma unroll
    for (int j = 0; j < 8; ++j) spool[rw][ck * 8 + j] = acc[j];
    __syncthreads();
    float pool = 0.f;
    #pragma unroll
    for (int w = 0; w < 8; ++w) pool += spool[w][t];

    // --- VN update: vn = vn_h + relu((vn_h + pool) @ W^T + b)
    float vh = __ldg(&vn_h[g * DIM + t]);
    sx[t] = vh + pool;
    __syncthreads();

    float acc0 = 0.f, acc1 = 0.f;
    #pragma unroll 8
    for (int k = 0; k < DIM; k += 2) {
        acc0 = fmaf(sx[k],     __ldg(&g_Wt[k * DIM + t]),       acc0);
        acc1 = fmaf(sx[k + 1], __ldg(&g_Wt[(k + 1) * DIM + t]), acc1);
    }
    float vn = vh + fmaxf(acc0 + acc1 + __ldg(&b[t]), 0.f);
    vn_out[g * DIM + t] = vn;
    svn[t] = vn;
    __syncthreads();

    float4 vnv = ((const float4*)svn)[ln];      // this lane's 4 columns of vn

    // --- pass 2 (reverse): h_out = h + vn. Tail hits sticky L2 lines;
    //     .cs loads/stores keep the stream from displacing them.
    const float4* h4 = (const float4*)h;
    float4*       o4 = (float4*)h_out;
    int cnt = end - (start + sg);
    if (cnt > 0) {
        int rr = start + sg + ((cnt - 1) >> 2) * 4;   // this warp's last row
        #pragma unroll 8
        for (; rr >= start; rr -= 4) {
            float4 v = __ldcs(&h4[rr * 32 + ln]);
            __stcs(&o4[rr * 32 + ln],
                   make_float4(v.x + vnv.x, v.y + vnv.y,
                               v.z + vnv.z, v.w + vnv.w));
        }
    }
}

// ---------------------------------------------------------------------------
// Launch: out = [vn_out (B*DIM floats) | h_out (N*DIM floats)]
// ---------------------------------------------------------------------------
extern "C" void kernel_launch(void* const* d_in, const int* in_sizes, int n_in,
                              void* d_out, int out_size) {
    const float* h    = (const float*)d_in[0];
    const float* vn_h = (const float*)d_in[1];
    const float* W    = (const float*)d_in[2];
    const float* b    = (const float*)d_in[3];
    const int*   seg  = (const int*)  d_in[4];

    float* out    = (float*)d_out;
    float* vn_out = out;                       // [B, DIM]
    float* h_out  = out + B_GRAPHS * DIM;      // [N, DIM]

    transpose_W_kernel<<<(DIM * DIM + 255) / 256, 256>>>(W);
    fused_vn_kernel<<<B_GRAPHS, DIM>>>(h, vn_h, b, seg, vn_out, h_out);
}

// round 16
// speedup vs baseline: 1.0164x; 1.0164x over previous
#include <cuda_runtime.h>
#include <cstdint>

#define N_NODES    1000000
#define DIM        128
#define B_GRAPHS   2048
#define NTHR       256               // 8 warps
#define NW         8
#define CROWS      32                // rows per chunk
#define ROWB       512               // bytes per row (128 fp32)
#define CBYTES     (CROWS * ROWB)    // 16 KB
#define NCHK       11                // cached chunks per graph
#define CACHE_ROWS (NCHK * CROWS)    // 352 rows = 176 KB
#define DYN_SMEM   (NCHK * CBYTES)   // 180224 B -> 1 block/SM

// Scratch (no cudaMalloc allowed)
__device__ float g_Wt[DIM * DIM];
__device__ int   g_bnd[B_GRAPHS + 1];

// ---------------------------------------------------------------------------
// Kernel 0a: transpose W.  g_Wt[k*DIM + j] = W[j*DIM + k]
// ---------------------------------------------------------------------------
__global__ void transpose_W_kernel(const float* __restrict__ W) {
    int i = blockIdx.x * blockDim.x + threadIdx.x;
    if (i < DIM * DIM) {
        int j = i >> 7;
        int k = i & (DIM - 1);
        g_Wt[k * DIM + j] = W[i];
    }
}

// ---------------------------------------------------------------------------
// Kernel 0b: segment boundaries from SORTED seg ids.
// g_bnd[g] = first index with seg[i] >= g;  g_bnd[B] = N.
// ---------------------------------------------------------------------------
__global__ void bounds_kernel(const int* __restrict__ seg) {
    int i = blockIdx.x * blockDim.x + threadIdx.x;
    if (i >= N_NODES) return;
    int s = seg[i];
    int p = (i == 0) ? -1 : seg[i - 1];
    for (int g = p + 1; g <= s; ++g) g_bnd[g] = i;
    if (i == N_NODES - 1)
        for (int g = s + 1; g <= B_GRAPHS; ++g) g_bnd[g] = N_NODES;
}

// ---- TMA / mbarrier helpers -------------------------------------------------
__device__ __forceinline__ uint32_t s2u(const void* p) {
    return (uint32_t)__cvta_generic_to_shared(p);
}
__device__ __forceinline__ void mbar_init1(uint32_t a) {
    asm volatile("mbarrier.init.shared.b64 [%0], 1;" :: "r"(a) : "memory");
}
__device__ __forceinline__ void tma_fetch(uint32_t mbar, uint32_t dst,
                                          const void* src, uint32_t bytes) {
    asm volatile("mbarrier.arrive.expect_tx.shared.b64 _, [%0], %1;"
                 :: "r"(mbar), "r"(bytes) : "memory");
    asm volatile("cp.async.bulk.shared::cta.global.mbarrier::complete_tx::bytes "
                 "[%0], [%1], %2, [%3];"
                 :: "r"(dst), "l"(src), "r"(bytes), "r"(mbar) : "memory");
}
__device__ __forceinline__ void mbar_wait(uint32_t a, uint32_t parity) {
    asm volatile(
        "{\n\t.reg .pred P;\n"
        "W%=:\n\t"
        "mbarrier.try_wait.parity.acquire.cta.shared::cta.b64 P, [%0], %1, 0x989680;\n\t"
        "@P bra D%=;\n\t"
        "bra W%=;\n"
        "D%=:\n\t}"
        :: "r"(a), "r"(parity) : "memory");
}

// ---------------------------------------------------------------------------
// Fused kernel: one block per graph, ONE block per SM (176KB smem cache).
// Reads h exactly once from DRAM:
//   pass 1: t0 fires NCHK independent 16KB bulk copies into dedicated slots
//           (176KB in flight, no ring). Meanwhile 8 warps LDG-sum the
//           overflow rows (>352); their lines stay L2-resident (10MB chip-
//           wide footprint). Then chunks are summed from smem as they land.
//   GEMM:   vn = vn_h + relu((vn_h + pool) @ W^T + b)
//   pass 2: cached rows written from smem (NO re-read); overflow rows
//           re-read from L2 (guaranteed hit). Stores .cs.
// ---------------------------------------------------------------------------
__global__ void __launch_bounds__(NTHR)
fused_vn_kernel(const float* __restrict__ h,
                const float* __restrict__ vn_h,
                const float* __restrict__ bias,
                float*       __restrict__ vn_out,
                float*       __restrict__ h_out) {
    extern __shared__ __align__(1024) float4 scache[];   // NCHK x 16 KB
    __shared__ float spool[NW][DIM];
    __shared__ float sx[DIM];
    __shared__ float svn[DIM];
    __shared__ __align__(8) unsigned long long smbar[NCHK];

    const int g  = blockIdx.x;
    const int t  = threadIdx.x;
    const int w  = t >> 5;      // warp 0..7
    const int ln = t & 31;      // float4 lane (columns 4ln..4ln+3)

    const uint32_t mb0  = s2u(&smbar[0]);
    const uint32_t buf0 = s2u(&scache[0]);

    if (t == 0) {
        #pragma unroll
        for (int i = 0; i < NCHK; ++i) mbar_init1(mb0 + 8u * i);
        asm volatile("fence.proxy.async.shared::cta;" ::: "memory");
    }
    __syncthreads();

    const int start  = g_bnd[g];
    const int end    = g_bnd[g + 1];
    const int rows   = end - start;
    const int cached = rows < CACHE_ROWS ? rows : CACHE_ROWS;
    const int nchk   = (cached + CROWS - 1) / CROWS;
    const int ovf0   = start + cached;
    const char* gsrc = (const char*)h + (size_t)start * ROWB;

    // --- fire all cache fetches (t0): 176KB outstanding, zero protocol
    if (t == 0) {
        for (int c = 0; c < nchk; ++c) {
            uint32_t bytes = (uint32_t)min(CROWS, cached - c * CROWS) * ROWB;
            tma_fetch(mb0 + 8u * c, buf0 + (uint32_t)c * CBYTES,
                      gsrc + (size_t)c * CBYTES, bytes);
        }
    }

    const float4* h4 = (const float4*)h;
    float4 a = make_float4(0.f, 0.f, 0.f, 0.f);

    // --- overflow rows: LDG-sum while TMA streams (lines park in L2)
    #pragma unroll 4
    for (int r = ovf0 + w; r < end; r += NW) {
        float4 v = __ldg(&h4[r * 32 + ln]);
        a.x += v.x; a.y += v.y; a.z += v.z; a.w += v.w;
    }

    // --- cached chunks: sum from smem as they arrive
    for (int c = 0; c < nchk; ++c) {
        mbar_wait(mb0 + 8u * c, 0);
        int rn = min(CROWS, cached - c * CROWS);
        const float4* sb = &scache[c * (CBYTES / 16)];
        #pragma unroll
        for (int r = w; r < CROWS; r += NW) {
            if (r < rn) {
                float4 v = sb[r * 32 + ln];
                a.x += v.x; a.y += v.y; a.z += v.z; a.w += v.w;
            }
        }
    }

    // --- reduce 8 warp partials -> pool[t] (threads 0..127)
    ((float4*)&spool[w][0])[ln] = a;
    __syncthreads();

    if (t < DIM) {
        float pool = 0.f;
        #pragma unroll
        for (int i = 0; i < NW; ++i) pool += spool[i][t];
        float vh = __ldg(&vn_h[g * DIM + t]);
        sx[t] = vh + pool;
    }
    __syncthreads();

    if (t < DIM) {
        float vh = __ldg(&vn_h[g * DIM + t]);
        float acc0 = 0.f, acc1 = 0.f;
        #pragma unroll 8
        for (int k = 0; k < DIM; k += 2) {
            acc0 = fmaf(sx[k],     __ldg(&g_Wt[k * DIM + t]),       acc0);
            acc1 = fmaf(sx[k + 1], __ldg(&g_Wt[(k + 1) * DIM + t]), acc1);
        }
        float vn = vh + fmaxf(acc0 + acc1 + __ldg(&bias[t]), 0.f);
        vn_out[g * DIM + t] = vn;
        svn[t] = vn;
    }
    __syncthreads();
    float4 vnv = ((const float4*)svn)[ln];

    // --- pass 2: cached rows straight from smem (no DRAM re-read)
    float4* o4 = (float4*)h_out;
    for (int c = 0; c < nchk; ++c) {
        int rn = min(CROWS, cached - c * CROWS);
        const float4* sb = &scache[c * (CBYTES / 16)];
        size_t obase = (size_t)(start + c * CROWS) * 32;
        #pragma unroll
        for (int r = w; r < CROWS; r += NW) {
            if (r < rn) {
                float4 v = sb[r * 32 + ln];
                __stcs(&o4[obase + r * 32 + ln],
                       make_float4(v.x + vnv.x, v.y + vnv.y,
                                   v.z + vnv.z, v.w + vnv.w));
            }
        }
    }
    // --- overflow rows: re-read (L2 hit), add, store
    #pragma unroll 4
    for (int r = ovf0 + w; r < end; r += NW) {
        float4 v = __ldg(&h4[r * 32 + ln]);
        __stcs(&o4[r * 32 + ln],
               make_float4(v.x + vnv.x, v.y + vnv.y,
                           v.z + vnv.z, v.w + vnv.w));
    }
}

// ---------------------------------------------------------------------------
// Launch: out = [vn_out (B*DIM floats) | h_out (N*DIM floats)]
// ---------------------------------------------------------------------------
extern "C" void kernel_launch(void* const* d_in, const int* in_sizes, int n_in,
                              void* d_out, int out_size) {
    const float* h    = (const float*)d_in[0];
    const float* vn_h = (const float*)d_in[1];
    const float* W    = (const float*)d_in[2];
    const float* b    = (const float*)d_in[3];
    const int*   seg  = (const int*)  d_in[4];

    float* out    = (float*)d_out;
    float* vn_out = out;                       // [B, DIM]
    float* h_out  = out + B_GRAPHS * DIM;      // [N, DIM]

    cudaFuncSetAttribute(fused_vn_kernel,
                         cudaFuncAttributeMaxDynamicSharedMemorySize, DYN_SMEM);

    transpose_W_kernel<<<(DIM * DIM + 255) / 256, 256>>>(W);
    bounds_kernel<<<(N_NODES + 255) / 256, 256>>>(seg);
    fused_vn_kernel<<<B_GRAPHS, NTHR, DYN_SMEM>>>(h, vn_h, b, vn_out, h_out);
}

// round 17
// speedup vs baseline: 1.0935x; 1.0759x over previous
#include <cuda_runtime.h>
#include <cstdint>

#define N_NODES    1000000
#define DIM        128
#define B_GRAPHS   2048
#define NTHR       256               // 8 warps per block
#define NW         8
#define CROWS      32                // rows per chunk
#define ROWB       512               // bytes per row (128 fp32)
#define CBYTES     (CROWS * ROWB)    // 16 KB
#define NCHK       6                 // cached chunks per graph (96 KB)
#define CACHE_ROWS (NCHK * CROWS)    // 192 rows
#define DYN_SMEM   (NCHK * CBYTES)   // 98304 B -> 2 blocks/SM (16 warps/SM)

// Scratch (no cudaMalloc allowed)
__device__ float g_Wt[DIM * DIM];
__device__ int   g_bnd[B_GRAPHS + 1];

// ---------------------------------------------------------------------------
// Kernel 0a: transpose W.  g_Wt[k*DIM + j] = W[j*DIM + k]
// ---------------------------------------------------------------------------
__global__ void transpose_W_kernel(const float* __restrict__ W) {
    int i = blockIdx.x * blockDim.x + threadIdx.x;
    if (i < DIM * DIM) {
        int j = i >> 7;
        int k = i & (DIM - 1);
        g_Wt[k * DIM + j] = W[i];
    }
}

// ---------------------------------------------------------------------------
// Kernel 0b: segment boundaries from SORTED seg ids.
// ---------------------------------------------------------------------------
__global__ void bounds_kernel(const int* __restrict__ seg) {
    int i = blockIdx.x * blockDim.x + threadIdx.x;
    if (i >= N_NODES) return;
    int s = seg[i];
    int p = (i == 0) ? -1 : seg[i - 1];
    for (int g = p + 1; g <= s; ++g) g_bnd[g] = i;
    if (i == N_NODES - 1)
        for (int g = s + 1; g <= B_GRAPHS; ++g) g_bnd[g] = N_NODES;
}

// ---- TMA / mbarrier helpers -------------------------------------------------
__device__ __forceinline__ uint32_t s2u(const void* p) {
    return (uint32_t)__cvta_generic_to_shared(p);
}
__device__ __forceinline__ void mbar_init1(uint32_t a) {
    asm volatile("mbarrier.init.shared.b64 [%0], 1;" :: "r"(a) : "memory");
}
__device__ __forceinline__ void tma_fetch(uint32_t mbar, uint32_t dst,
                                          const void* src, uint32_t bytes) {
    asm volatile("mbarrier.arrive.expect_tx.shared.b64 _, [%0], %1;"
                 :: "r"(mbar), "r"(bytes) : "memory");
    asm volatile("cp.async.bulk.shared::cta.global.mbarrier::complete_tx::bytes "
                 "[%0], [%1], %2, [%3];"
                 :: "r"(dst), "l"(src), "r"(bytes), "r"(mbar) : "memory");
}
__device__ __forceinline__ void mbar_wait(uint32_t a, uint32_t parity) {
    asm volatile(
        "{\n\t.reg .pred P;\n"
        "W%=:\n\t"
        "mbarrier.try_wait.parity.acquire.cta.shared::cta.b64 P, [%0], %1, 0x989680;\n\t"
        "@P bra D%=;\n\t"
        "bra W%=;\n"
        "D%=:\n\t}"
        :: "r"(a), "r"(parity) : "memory");
}

// ---------------------------------------------------------------------------
// Fused kernel: one block per graph, TWO blocks per SM (96KB smem cache each).
// h is read from DRAM exactly once:
//   pass 1: t0 fires NCHK independent 16KB bulk copies into dedicated slots
//           (192KB/SM in flight). Meanwhile 8 warps LDG-sum the ~296
//           overflow rows; those lines stay L2-resident (45MB chip-wide).
//           Then cached chunks are summed from smem as they land.
//   GEMM:   vn = vn_h + relu((vn_h + pool) @ W^T + b)
//   pass 2: cached rows written from smem (NO re-read); overflow rows
//           re-read from L2 (guaranteed hit, footprint << L2). Stores .cs.
// 16 warps/SM doubles R16's consumer/store issue capacity (the measured
// limiter: 8 warps -> 4.3 TB/s, 16 -> ~5.2, 40 -> 5.9).
// ---------------------------------------------------------------------------
__global__ void __launch_bounds__(NTHR)
fused_vn_kernel(const float* __restrict__ h,
                const float* __restrict__ vn_h,
                const float* __restrict__ bias,
                float*       __restrict__ vn_out,
                float*       __restrict__ h_out) {
    extern __shared__ __align__(1024) float4 scache[];   // NCHK x 16 KB
    __shared__ float spool[NW][DIM];
    __shared__ float sx[DIM];
    __shared__ float svn[DIM];
    __shared__ __align__(8) unsigned long long smbar[NCHK];

    const int g  = blockIdx.x;
    const int t  = threadIdx.x;
    const int w  = t >> 5;      // warp 0..7
    const int ln = t & 31;      // float4 lane (columns 4ln..4ln+3)

    const uint32_t mb0  = s2u(&smbar[0]);
    const uint32_t buf0 = s2u(&scache[0]);

    if (t == 0) {
        #pragma unroll
        for (int i = 0; i < NCHK; ++i) mbar_init1(mb0 + 8u * i);
        asm volatile("fence.proxy.async.shared::cta;" ::: "memory");
    }
    __syncthreads();

    const int start  = g_bnd[g];
    const int end    = g_bnd[g + 1];
    const int rows   = end - start;
    const int cached = rows < CACHE_ROWS ? rows : CACHE_ROWS;
    const int nchk   = (cached + CROWS - 1) / CROWS;
    const int ovf0   = start + cached;
    const char* gsrc = (const char*)h + (size_t)start * ROWB;

    // --- fire all cache fetches (t0): 96KB outstanding per block
    if (t == 0) {
        for (int c = 0; c < nchk; ++c) {
            uint32_t bytes = (uint32_t)min(CROWS, cached - c * CROWS) * ROWB;
            tma_fetch(mb0 + 8u * c, buf0 + (uint32_t)c * CBYTES,
                      gsrc + (size_t)c * CBYTES, bytes);
        }
    }

    const float4* h4 = (const float4*)h;
    float4 a = make_float4(0.f, 0.f, 0.f, 0.f);

    // --- overflow rows: LDG-sum while TMA streams (lines park in L2)
    #pragma unroll 4
    for (int r = ovf0 + w; r < end; r += NW) {
        float4 v = __ldg(&h4[r * 32 + ln]);
        a.x += v.x; a.y += v.y; a.z += v.z; a.w += v.w;
    }

    // --- cached chunks: sum from smem as they arrive
    for (int c = 0; c < nchk; ++c) {
        mbar_wait(mb0 + 8u * c, 0);
        int rn = min(CROWS, cached - c * CROWS);
        const float4* sb = &scache[c * (CBYTES / 16)];
        #pragma unroll
        for (int r = w; r < CROWS; r += NW) {
            if (r < rn) {
                float4 v = sb[r * 32 + ln];
                a.x += v.x; a.y += v.y; a.z += v.z; a.w += v.w;
            }
        }
    }

    // --- reduce 8 warp partials -> pool[t] (threads 0..127)
    ((float4*)&spool[w][0])[ln] = a;
    __syncthreads();

    if (t < DIM) {
        float pool = 0.f;
        #pragma unroll
        for (int i = 0; i < NW; ++i) pool += spool[i][t];
        sx[t] = __ldg(&vn_h[g * DIM + t]) + pool;
    }
    __syncthreads();

    if (t < DIM) {
        float vh = __ldg(&vn_h[g * DIM + t]);
        float acc0 = 0.f, acc1 = 0.f;
        #pragma unroll 8
        for (int k = 0; k < DIM; k += 2) {
            acc0 = fmaf(sx[k],     __ldg(&g_Wt[k * DIM + t]),       acc0);
            acc1 = fmaf(sx[k + 1], __ldg(&g_Wt[(k + 1) * DIM + t]), acc1);
        }
        float vn = vh + fmaxf(acc0 + acc1 + __ldg(&bias[t]), 0.f);
        vn_out[g * DIM + t] = vn;
        svn[t] = vn;
    }
    __syncthreads();
    float4 vnv = ((const float4*)svn)[ln];

    // --- pass 2a: cached rows straight from smem (no DRAM re-read)
    float4* o4 = (float4*)h_out;
    for (int c = 0; c < nchk; ++c) {
        int rn = min(CROWS, cached - c * CROWS);
        const float4* sb = &scache[c * (CBYTES / 16)];
        size_t obase = (size_t)(start + c * CROWS) * 32;
        #pragma unroll
        for (int r = w; r < CROWS; r += NW) {
            if (r < rn) {
                float4 v = sb[r * 32 + ln];
                __stcs(&o4[obase + r * 32 + ln],
                       make_float4(v.x + vnv.x, v.y + vnv.y,
                                   v.z + vnv.z, v.w + vnv.w));
            }
        }
    }
    // --- pass 2b: overflow rows re-read (L2 hit), add, store
    #pragma unroll 4
    for (int r = ovf0 + w; r < end; r += NW) {
        float4 v = __ldg(&h4[r * 32 + ln]);
        __stcs(&o4[r * 32 + ln],
               make_float4(v.x + vnv.x, v.y + vnv.y,
                           v.z + vnv.z, v.w + vnv.w));
    }
}

// ---------------------------------------------------------------------------
// Launch: out = [vn_out (B*DIM floats) | h_out (N*DIM floats)]
// ---------------------------------------------------------------------------
extern "C" void kernel_launch(void* const* d_in, const int* in_sizes, int n_in,
                              void* d_out, int out_size) {
    const float* h    = (const float*)d_in[0];
    const float* vn_h = (const float*)d_in[1];
    const float* W    = (const float*)d_in[2];
    const float* b    = (const float*)d_in[3];
    const int*   seg  = (const int*)  d_in[4];

    float* out    = (float*)d_out;
    float* vn_out = out;                       // [B, DIM]
    float* h_out  = out + B_GRAPHS * DIM;      // [N, DIM]

    cudaFuncSetAttribute(fused_vn_kernel,
                         cudaFuncAttributeMaxDynamicSharedMemorySize, DYN_SMEM);

    transpose_W_kernel<<<(DIM * DIM + 255) / 256, 256>>>(W);
    bounds_kernel<<<(N_NODES + 255) / 256, 256>>>(seg);
    fused_vn_kernel<<<B_GRAPHS, NTHR, DYN_SMEM>>>(h, vn_h, b, vn_out, h_out);
}